// round 2
// baseline (speedup 1.0000x reference)
#include <cuda_runtime.h>
#include <cstdint>

#define N_NODES 100000
#define NE      1600000
#define D       128

// Scratch (allocation-free: __device__ globals)
__device__ __align__(16) float g_agg[(size_t)N_NODES * D];   // 51.2 MB
__device__ float g_deg[N_NODES];
__device__ int   g_is64;

// ---------------------------------------------------------------------------
// Probe: edge_list may be int64 (reference asks) or int32 (default JAX x64-off
// downcast). First edges are the ring: src = 0,1,2,... so for an int32 layout
// the odd 32-bit words are 1,3,5,... (nonzero); for int64 they are the high
// words of small nonnegative values (all zero).
// ---------------------------------------------------------------------------
__global__ void probe_kernel(const int* __restrict__ ei) {
    int acc = 0;
#pragma unroll
    for (int i = 1; i < 32; i += 2) acc |= ei[i];
    g_is64 = (acc == 0) ? 1 : 0;
}

// ---------------------------------------------------------------------------
// Init: agg = X, deg = 0
// ---------------------------------------------------------------------------
__global__ void init_kernel(const float4* __restrict__ X4) {
    int i = blockIdx.x * blockDim.x + threadIdx.x;
    if (i < N_NODES * (D / 4)) ((float4*)g_agg)[i] = X4[i];
    if (i < N_NODES) g_deg[i] = 0.0f;
}

// ---------------------------------------------------------------------------
// Edge scatter: one warp per edge. Each lane owns 4 contiguous floats of the
// 128-float row; red.global.add.v4.f32 does a 16B no-return reduction.
// ---------------------------------------------------------------------------
__global__ void edge_kernel(const void* __restrict__ ei_raw,
                            const float* __restrict__ X) {
    int w    = (blockIdx.x * blockDim.x + threadIdx.x) >> 5;
    int lane = threadIdx.x & 31;
    if (w >= NE) return;

    int s, d;
    if (g_is64) {
        const long long* ei = (const long long*)ei_raw;
        s = (int)ei[w];
        d = (int)ei[NE + w];
    } else {
        const int* ei = (const int*)ei_raw;
        s = ei[w];
        d = ei[NE + w];
    }

    float4 vs = ((const float4*)(X + (size_t)s * D))[lane];
    float4 vd = ((const float4*)(X + (size_t)d * D))[lane];

    float* pd = g_agg + (size_t)d * D + lane * 4;
    float* ps = g_agg + (size_t)s * D + lane * 4;
    asm volatile("red.global.add.v4.f32 [%0], {%1,%2,%3,%4};"
                 :: "l"(pd), "f"(vs.x), "f"(vs.y), "f"(vs.z), "f"(vs.w)
                 : "memory");
    asm volatile("red.global.add.v4.f32 [%0], {%1,%2,%3,%4};"
                 :: "l"(ps), "f"(vd.x), "f"(vd.y), "f"(vd.z), "f"(vd.w)
                 : "memory");

    if (lane == 0) {
        atomicAdd(g_deg + s, 1.0f);
        atomicAdd(g_deg + d, 1.0f);
    }
}

// ---------------------------------------------------------------------------
// GEMM: out = relu((agg / deg) @ W)
// Block = 256 threads (8 warps), 32 rows per block (4 per warp).
// W (128x128 f32, 64 KB) + 32 agg rows (16 KB) staged in dynamic smem.
// Each lane computes a 4-row x 4-col tile: per 4 k's, 8 LDS.128 + 64 FFMA.
// Per-row 1/deg scaling folded into the epilogue (distributes over the dot).
// ---------------------------------------------------------------------------
#define ROWS_PER_BLOCK 32

__global__ void __launch_bounds__(256, 2)
gemm_kernel(const float* __restrict__ W, float* __restrict__ out) {
    extern __shared__ float sh[];
    float* w_sh = sh;             // D*D floats
    float* a_sh = sh + D * D;     // ROWS_PER_BLOCK*D floats

    int tid  = threadIdx.x;
    int row0 = blockIdx.x * ROWS_PER_BLOCK;

    // Stage W (4096 float4, 16 per thread)
    const float4* W4   = (const float4*)W;
    float4*       wsh4 = (float4*)w_sh;
#pragma unroll
    for (int i = 0; i < 16; i++) wsh4[tid + i * 256] = W4[tid + i * 256];

    // Stage 32 contiguous agg rows (1024 float4, 4 per thread)
    const float4* A4   = (const float4*)(g_agg + (size_t)row0 * D);
    float4*       ash4 = (float4*)a_sh;
#pragma unroll
    for (int i = 0; i < 4; i++) ash4[tid + i * 256] = A4[tid + i * 256];
    __syncthreads();

    int warp  = tid >> 5;
    int lane  = tid & 31;
    int rbase = warp * 4;             // 4 rows per warp

    float4 acc[4];
#pragma unroll
    for (int r = 0; r < 4; r++) acc[r] = make_float4(0.f, 0.f, 0.f, 0.f);

    const float4* wv = (const float4*)w_sh;   // row k = 32 float4
    for (int k = 0; k < D; k += 4) {
        float4 w0 = wv[(k + 0) * 32 + lane];
        float4 w1 = wv[(k + 1) * 32 + lane];
        float4 w2 = wv[(k + 2) * 32 + lane];
        float4 w3 = wv[(k + 3) * 32 + lane];
#pragma unroll
        for (int r = 0; r < 4; r++) {
            float4 a4 = ((const float4*)(a_sh + (rbase + r) * D))[k >> 2];
            acc[r].x += a4.x * w0.x + a4.y * w1.x + a4.z * w2.x + a4.w * w3.x;
            acc[r].y += a4.x * w0.y + a4.y * w1.y + a4.z * w2.y + a4.w * w3.y;
            acc[r].z += a4.x * w0.z + a4.y * w1.z + a4.z * w2.z + a4.w * w3.z;
            acc[r].w += a4.x * w0.w + a4.y * w1.w + a4.z * w2.w + a4.w * w3.w;
        }
    }

#pragma unroll
    for (int r = 0; r < 4; r++) {
        int row = row0 + rbase + r;
        float inv = 1.0f / g_deg[row];
        float4 o;
        o.x = fmaxf(acc[r].x * inv, 0.0f);
        o.y = fmaxf(acc[r].y * inv, 0.0f);
        o.z = fmaxf(acc[r].z * inv, 0.0f);
        o.w = fmaxf(acc[r].w * inv, 0.0f);
        ((float4*)(out + (size_t)row * D))[lane] = o;
    }
}

// ---------------------------------------------------------------------------
extern "C" void kernel_launch(void* const* d_in, const int* in_sizes, int n_in,
                              void* d_out, int out_size) {
    const float* X  = (const float*)d_in[0];
    const float* W  = (const float*)d_in[1];
    const void*  EI = d_in[2];
    float*       out = (float*)d_out;

    probe_kernel<<<1, 1>>>((const int*)EI);

    int init_threads = N_NODES * (D / 4);
    init_kernel<<<(init_threads + 255) / 256, 256>>>((const float4*)X);

    edge_kernel<<<(NE + 7) / 8, 256>>>(EI, X);

    int smem = (D * D + ROWS_PER_BLOCK * D) * (int)sizeof(float);  // 80 KB
    cudaFuncSetAttribute(gemm_kernel,
                         cudaFuncAttributeMaxDynamicSharedMemorySize, smem);
    gemm_kernel<<<N_NODES / ROWS_PER_BLOCK, 256, smem>>>(W, out);
}

// round 3
// speedup vs baseline: 1.5341x; 1.5341x over previous
#include <cuda_runtime.h>
#include <cstdint>

#define N_NODES 100000
#define NE      1600000
#define D       128
#define NB      ((N_NODES + 255) / 256)   // 391 scan blocks

// Scratch (__device__ globals; no allocation)
__device__ __align__(16) float g_Y[(size_t)N_NODES * D];   // 51.2 MB, Y = X@W
__device__ int g_degi[N_NODES];
__device__ int g_rowstart[N_NODES];
__device__ int g_cursor[N_NODES];
__device__ int g_adj[2 * NE];                               // 12.8 MB
__device__ int g_bsum[512];
__device__ int g_is64;

// ---------------------------------------------------------------------------
// Probe edge dtype: int64 (high words of ring edges are 0) vs int32.
// ---------------------------------------------------------------------------
__global__ void probe_kernel(const int* __restrict__ ei) {
    int acc = 0;
#pragma unroll
    for (int i = 1; i < 32; i += 2) acc |= ei[i];
    g_is64 = (acc == 0) ? 1 : 0;
}

__device__ __forceinline__ void load_edge(const void* ei_raw, int e, int& s, int& d) {
    if (g_is64) {
        const long long* ei = (const long long*)ei_raw;
        s = (int)ei[e];
        d = (int)ei[NE + e];
    } else {
        const int* ei = (const int*)ei_raw;
        s = ei[e];
        d = ei[NE + e];
    }
}

// ---------------------------------------------------------------------------
// CSR build
// ---------------------------------------------------------------------------
__global__ void zero_kernel() {
    int i = blockIdx.x * blockDim.x + threadIdx.x;
    if (i < N_NODES) g_degi[i] = 0;
}

__global__ void count_kernel(const void* __restrict__ ei_raw) {
    int e = blockIdx.x * blockDim.x + threadIdx.x;
    if (e >= NE) return;
    int s, d;
    load_edge(ei_raw, e, s, d);
    atomicAdd(&g_degi[s], 1);
    atomicAdd(&g_degi[d], 1);
}

// Block-local inclusive scan of degrees; write (incl - v) and block sum.
__global__ void scan1_kernel() {
    __shared__ int sh[256];
    int tid = threadIdx.x;
    int i   = blockIdx.x * 256 + tid;
    int v   = (i < N_NODES) ? g_degi[i] : 0;
    sh[tid] = v;
    __syncthreads();
#pragma unroll
    for (int off = 1; off < 256; off <<= 1) {
        int t = (tid >= off) ? sh[tid - off] : 0;
        __syncthreads();
        sh[tid] += t;
        __syncthreads();
    }
    if (i < N_NODES) g_rowstart[i] = sh[tid] - v;
    if (tid == 255) g_bsum[blockIdx.x] = sh[255];
}

// Scan of the 391 block sums (exclusive), single block of 512.
__global__ void scan2_kernel() {
    __shared__ int sh[512];
    int tid = threadIdx.x;
    int v   = (tid < NB) ? g_bsum[tid] : 0;
    sh[tid] = v;
    __syncthreads();
#pragma unroll
    for (int off = 1; off < 512; off <<= 1) {
        int t = (tid >= off) ? sh[tid - off] : 0;
        __syncthreads();
        sh[tid] += t;
        __syncthreads();
    }
    if (tid < NB) g_bsum[tid] = sh[tid] - v;   // exclusive
}

__global__ void scan3_kernel() {
    int i = blockIdx.x * 256 + threadIdx.x;
    if (i >= N_NODES) return;
    int r = g_rowstart[i] + g_bsum[blockIdx.x];
    g_rowstart[i] = r;
    g_cursor[i]   = r;
}

__global__ void fill_kernel(const void* __restrict__ ei_raw) {
    int e = blockIdx.x * blockDim.x + threadIdx.x;
    if (e >= NE) return;
    int s, d;
    load_edge(ei_raw, e, s, d);
    int p = atomicAdd(&g_cursor[s], 1);
    g_adj[p] = d;
    int q = atomicAdd(&g_cursor[d], 1);
    g_adj[q] = s;
}

// ---------------------------------------------------------------------------
// GEMM: Y = X @ W   (no scaling/relu — moved to gather)
// 8 warps/block, 5 tiles of 32 rows per block (grid 625), W staged once.
// ---------------------------------------------------------------------------
#define TILES_PER_BLOCK 5

__global__ void __launch_bounds__(256, 2)
gemm_kernel(const float* __restrict__ X, const float* __restrict__ W) {
    extern __shared__ float sh[];
    float* w_sh = sh;             // D*D
    float* a_sh = sh + D * D;     // 32*D

    int tid = threadIdx.x;

    // Stage W (4096 float4)
    const float4* W4   = (const float4*)W;
    float4*       wsh4 = (float4*)w_sh;
#pragma unroll
    for (int i = 0; i < 16; i++) wsh4[tid + i * 256] = W4[tid + i * 256];

    int warp  = tid >> 5;
    int lane  = tid & 31;
    int rbase = warp * 4;
    const float4* wv = (const float4*)w_sh;

    for (int tile = 0; tile < TILES_PER_BLOCK; tile++) {
        int row0 = (blockIdx.x * TILES_PER_BLOCK + tile) * 32;

        __syncthreads();   // a_sh free from previous tile
        const float4* A4   = (const float4*)(X + (size_t)row0 * D);
        float4*       ash4 = (float4*)a_sh;
#pragma unroll
        for (int i = 0; i < 4; i++) ash4[tid + i * 256] = A4[tid + i * 256];
        __syncthreads();

        float4 acc[4];
#pragma unroll
        for (int r = 0; r < 4; r++) acc[r] = make_float4(0.f, 0.f, 0.f, 0.f);

        for (int k = 0; k < D; k += 4) {
            float4 w0 = wv[(k + 0) * 32 + lane];
            float4 w1 = wv[(k + 1) * 32 + lane];
            float4 w2 = wv[(k + 2) * 32 + lane];
            float4 w3 = wv[(k + 3) * 32 + lane];
#pragma unroll
            for (int r = 0; r < 4; r++) {
                float4 a4 = ((const float4*)(a_sh + (rbase + r) * D))[k >> 2];
                acc[r].x += a4.x * w0.x + a4.y * w1.x + a4.z * w2.x + a4.w * w3.x;
                acc[r].y += a4.x * w0.y + a4.y * w1.y + a4.z * w2.y + a4.w * w3.y;
                acc[r].z += a4.x * w0.z + a4.y * w1.z + a4.z * w2.z + a4.w * w3.z;
                acc[r].w += a4.x * w0.w + a4.y * w1.w + a4.z * w2.w + a4.w * w3.w;
            }
        }

#pragma unroll
        for (int r = 0; r < 4; r++) {
            int row = row0 + rbase + r;
            ((float4*)g_Y)[(size_t)row * 32 + lane] = acc[r];
        }
    }
}

// ---------------------------------------------------------------------------
// Gather: out[i] = relu((Y[i] + sum_{j in adj[i]} Y[j]) / deg[i])
// One warp per node; coalesced 512B row reads, L2-resident.
// ---------------------------------------------------------------------------
__global__ void __launch_bounds__(256)
gather_kernel(float* __restrict__ out) {
    int w    = (blockIdx.x * blockDim.x + threadIdx.x) >> 5;
    int lane = threadIdx.x & 31;
    if (w >= N_NODES) return;

    int base = g_rowstart[w];
    int degn = g_degi[w];

    const float4* Y4 = (const float4*)g_Y;
    float4 acc = Y4[(size_t)w * 32 + lane];

    for (int t = 0; t < degn; t += 32) {
        int cnt   = min(32, degn - t);
        int myidx = (lane < cnt) ? g_adj[base + t + lane] : 0;
#pragma unroll 8
        for (int k = 0; k < cnt; k++) {
            int u = __shfl_sync(0xffffffffu, myidx, k);
            float4 v = Y4[(size_t)u * 32 + lane];
            acc.x += v.x; acc.y += v.y; acc.z += v.z; acc.w += v.w;
        }
    }

    float inv = 1.0f / (float)degn;
    float4 o;
    o.x = fmaxf(acc.x * inv, 0.0f);
    o.y = fmaxf(acc.y * inv, 0.0f);
    o.z = fmaxf(acc.z * inv, 0.0f);
    o.w = fmaxf(acc.w * inv, 0.0f);
    ((float4*)out)[(size_t)w * 32 + lane] = o;
}

// ---------------------------------------------------------------------------
extern "C" void kernel_launch(void* const* d_in, const int* in_sizes, int n_in,
                              void* d_out, int out_size) {
    const float* X   = (const float*)d_in[0];
    const float* W   = (const float*)d_in[1];
    const void*  EI  = d_in[2];
    float*       out = (float*)d_out;

    probe_kernel<<<1, 1>>>((const int*)EI);

    zero_kernel<<<NB, 256>>>();
    count_kernel<<<(NE + 255) / 256, 256>>>(EI);
    scan1_kernel<<<NB, 256>>>();
    scan2_kernel<<<1, 512>>>();
    scan3_kernel<<<NB, 256>>>();
    fill_kernel<<<(NE + 255) / 256, 256>>>(EI);

    int smem = (D * D + 32 * D) * (int)sizeof(float);   // 80 KB
    cudaFuncSetAttribute(gemm_kernel,
                         cudaFuncAttributeMaxDynamicSharedMemorySize, smem);
    gemm_kernel<<<N_NODES / (32 * TILES_PER_BLOCK), 256, smem>>>(X, W);

    gather_kernel<<<(N_NODES * 32 + 255) / 256, 256>>>(out);
}

// round 4
// speedup vs baseline: 1.7324x; 1.1293x over previous
#include <cuda_runtime.h>
#include <cuda_fp16.h>
#include <cstdint>

#define N_NODES 100000
#define NE      1600000
#define D       128
#define NB      ((N_NODES + 255) / 256)   // 391 scan blocks

// Scratch (__device__ globals; no allocation)
__device__ __align__(16) __half g_Yh[(size_t)N_NODES * D];  // 25.6 MB, Y = X@W in fp16
__device__ int g_degi[N_NODES];
__device__ int g_rowstart[N_NODES];
__device__ int g_cursor[N_NODES];
__device__ int g_adj[2 * NE];                               // 12.8 MB
__device__ int g_bsum[512];
__device__ int g_is64;

// ---------------------------------------------------------------------------
// Probe edge dtype: int64 (high words of ring edges are 0) vs int32.
// ---------------------------------------------------------------------------
__global__ void probe_kernel(const int* __restrict__ ei) {
    int acc = 0;
#pragma unroll
    for (int i = 1; i < 32; i += 2) acc |= ei[i];
    g_is64 = (acc == 0) ? 1 : 0;
}

__device__ __forceinline__ void load_edge(const void* ei_raw, int e, int& s, int& d) {
    if (g_is64) {
        const long long* ei = (const long long*)ei_raw;
        s = (int)ei[e];
        d = (int)ei[NE + e];
    } else {
        const int* ei = (const int*)ei_raw;
        s = ei[e];
        d = ei[NE + e];
    }
}

// ---------------------------------------------------------------------------
// CSR build
// ---------------------------------------------------------------------------
__global__ void zero_kernel() {
    int i = blockIdx.x * blockDim.x + threadIdx.x;
    if (i < N_NODES) g_degi[i] = 0;
}

__global__ void count_kernel(const void* __restrict__ ei_raw) {
    int e = blockIdx.x * blockDim.x + threadIdx.x;
    if (e >= NE) return;
    int s, d;
    load_edge(ei_raw, e, s, d);
    atomicAdd(&g_degi[s], 1);
    atomicAdd(&g_degi[d], 1);
}

__global__ void scan1_kernel() {
    __shared__ int sh[256];
    int tid = threadIdx.x;
    int i   = blockIdx.x * 256 + tid;
    int v   = (i < N_NODES) ? g_degi[i] : 0;
    sh[tid] = v;
    __syncthreads();
#pragma unroll
    for (int off = 1; off < 256; off <<= 1) {
        int t = (tid >= off) ? sh[tid - off] : 0;
        __syncthreads();
        sh[tid] += t;
        __syncthreads();
    }
    if (i < N_NODES) g_rowstart[i] = sh[tid] - v;
    if (tid == 255) g_bsum[blockIdx.x] = sh[255];
}

__global__ void scan2_kernel() {
    __shared__ int sh[512];
    int tid = threadIdx.x;
    int v   = (tid < NB) ? g_bsum[tid] : 0;
    sh[tid] = v;
    __syncthreads();
#pragma unroll
    for (int off = 1; off < 512; off <<= 1) {
        int t = (tid >= off) ? sh[tid - off] : 0;
        __syncthreads();
        sh[tid] += t;
        __syncthreads();
    }
    if (tid < NB) g_bsum[tid] = sh[tid] - v;   // exclusive
}

__global__ void scan3_kernel() {
    int i = blockIdx.x * 256 + threadIdx.x;
    if (i >= N_NODES) return;
    int r = g_rowstart[i] + g_bsum[blockIdx.x];
    g_rowstart[i] = r;
    g_cursor[i]   = r;
}

__global__ void fill_kernel(const void* __restrict__ ei_raw) {
    int e = blockIdx.x * blockDim.x + threadIdx.x;
    if (e >= NE) return;
    int s, d;
    load_edge(ei_raw, e, s, d);
    int p = atomicAdd(&g_cursor[s], 1);
    g_adj[p] = d;
    int q = atomicAdd(&g_cursor[d], 1);
    g_adj[q] = s;
}

// ---------------------------------------------------------------------------
// GEMM: Yh = half(X @ W)
// W in smem (64 KB dynamic). A rows read directly from global (warp-uniform
// addresses -> L1-broadcast, ~2 KB live per warp). 3 blocks/SM.
// 8 warps/block x 4 rows/warp x 5 tiles -> 160 rows/block, grid 625.
// ---------------------------------------------------------------------------
#define TILES_PER_BLOCK 5

__global__ void __launch_bounds__(256, 3)
gemm_kernel(const float* __restrict__ X, const float* __restrict__ W) {
    extern __shared__ float w_sh[];   // D*D floats

    int tid = threadIdx.x;

    const float4* W4   = (const float4*)W;
    float4*       wsh4 = (float4*)w_sh;
#pragma unroll
    for (int i = 0; i < 16; i++) wsh4[tid + i * 256] = W4[tid + i * 256];
    __syncthreads();

    int warp  = tid >> 5;
    int lane  = tid & 31;
    const float4* wv = (const float4*)w_sh;

#pragma unroll 1
    for (int tile = 0; tile < TILES_PER_BLOCK; tile++) {
        int row0 = (blockIdx.x * TILES_PER_BLOCK + tile) * 32 + warp * 4;
        const float4* A0 = (const float4*)(X + (size_t)(row0 + 0) * D);
        const float4* A1 = (const float4*)(X + (size_t)(row0 + 1) * D);
        const float4* A2 = (const float4*)(X + (size_t)(row0 + 2) * D);
        const float4* A3 = (const float4*)(X + (size_t)(row0 + 3) * D);

        float4 acc[4];
#pragma unroll
        for (int r = 0; r < 4; r++) acc[r] = make_float4(0.f, 0.f, 0.f, 0.f);

#pragma unroll 4
        for (int k = 0; k < D; k += 4) {
            float4 w0 = wv[(k + 0) * 32 + lane];
            float4 w1 = wv[(k + 1) * 32 + lane];
            float4 w2 = wv[(k + 2) * 32 + lane];
            float4 w3 = wv[(k + 3) * 32 + lane];
            float4 a0 = __ldg(A0 + (k >> 2));
            float4 a1 = __ldg(A1 + (k >> 2));
            float4 a2 = __ldg(A2 + (k >> 2));
            float4 a3 = __ldg(A3 + (k >> 2));

            acc[0].x += a0.x * w0.x + a0.y * w1.x + a0.z * w2.x + a0.w * w3.x;
            acc[0].y += a0.x * w0.y + a0.y * w1.y + a0.z * w2.y + a0.w * w3.y;
            acc[0].z += a0.x * w0.z + a0.y * w1.z + a0.z * w2.z + a0.w * w3.z;
            acc[0].w += a0.x * w0.w + a0.y * w1.w + a0.z * w2.w + a0.w * w3.w;

            acc[1].x += a1.x * w0.x + a1.y * w1.x + a1.z * w2.x + a1.w * w3.x;
            acc[1].y += a1.x * w0.y + a1.y * w1.y + a1.z * w2.y + a1.w * w3.y;
            acc[1].z += a1.x * w0.z + a1.y * w1.z + a1.z * w2.z + a1.w * w3.z;
            acc[1].w += a1.x * w0.w + a1.y * w1.w + a1.z * w2.w + a1.w * w3.w;

            acc[2].x += a2.x * w0.x + a2.y * w1.x + a2.z * w2.x + a2.w * w3.x;
            acc[2].y += a2.x * w0.y + a2.y * w1.y + a2.z * w2.y + a2.w * w3.y;
            acc[2].z += a2.x * w0.z + a2.y * w1.z + a2.z * w2.z + a2.w * w3.z;
            acc[2].w += a2.x * w0.w + a2.y * w1.w + a2.z * w2.w + a2.w * w3.w;

            acc[3].x += a3.x * w0.x + a3.y * w1.x + a3.z * w2.x + a3.w * w3.x;
            acc[3].y += a3.x * w0.y + a3.y * w1.y + a3.z * w2.y + a3.w * w3.y;
            acc[3].z += a3.x * w0.z + a3.y * w1.z + a3.z * w2.z + a3.w * w3.z;
            acc[3].w += a3.x * w0.w + a3.y * w1.w + a3.z * w2.w + a3.w * w3.w;
        }

#pragma unroll
        for (int r = 0; r < 4; r++) {
            __half2 h01 = __float22half2_rn(make_float2(acc[r].x, acc[r].y));
            __half2 h23 = __float22half2_rn(make_float2(acc[r].z, acc[r].w));
            uint2 packed;
            packed.x = *(unsigned*)&h01;
            packed.y = *(unsigned*)&h23;
            ((uint2*)(g_Yh + (size_t)(row0 + r) * D))[lane] = packed;
        }
    }
}

// ---------------------------------------------------------------------------
// Gather: out[i] = relu((Y[i] + sum_{j in adj[i]} Y[j]) / deg[i])
// One warp per node. Rows are 256B of fp16; lane loads uint2 (4 halves),
// accumulates in fp32.
// ---------------------------------------------------------------------------
__device__ __forceinline__ void acc_half4(float4& acc, uint2 raw) {
    __half2 h01 = *(__half2*)&raw.x;
    __half2 h23 = *(__half2*)&raw.y;
    float2 f01 = __half22float2(h01);
    float2 f23 = __half22float2(h23);
    acc.x += f01.x; acc.y += f01.y; acc.z += f23.x; acc.w += f23.y;
}

__global__ void __launch_bounds__(256)
gather_kernel(float* __restrict__ out) {
    int w    = (blockIdx.x * blockDim.x + threadIdx.x) >> 5;
    int lane = threadIdx.x & 31;
    if (w >= N_NODES) return;

    int base = g_rowstart[w];
    int degn = g_degi[w];

    const uint2* Y2 = (const uint2*)g_Yh;
    float4 acc = make_float4(0.f, 0.f, 0.f, 0.f);
    acc_half4(acc, __ldg(Y2 + (size_t)w * 32 + lane));   // self term

    for (int t = 0; t < degn; t += 32) {
        int cnt   = min(32, degn - t);
        int myidx = (lane < cnt) ? g_adj[base + t + lane] : 0;
#pragma unroll 8
        for (int k = 0; k < cnt; k++) {
            int u = __shfl_sync(0xffffffffu, myidx, k);
            acc_half4(acc, __ldg(Y2 + (size_t)u * 32 + lane));
        }
    }

    float inv = 1.0f / (float)degn;
    float4 o;
    o.x = fmaxf(acc.x * inv, 0.0f);
    o.y = fmaxf(acc.y * inv, 0.0f);
    o.z = fmaxf(acc.z * inv, 0.0f);
    o.w = fmaxf(acc.w * inv, 0.0f);
    ((float4*)out)[(size_t)w * 32 + lane] = o;
}

// ---------------------------------------------------------------------------
extern "C" void kernel_launch(void* const* d_in, const int* in_sizes, int n_in,
                              void* d_out, int out_size) {
    const float* X   = (const float*)d_in[0];
    const float* W   = (const float*)d_in[1];
    const void*  EI  = d_in[2];
    float*       out = (float*)d_out;

    probe_kernel<<<1, 1>>>((const int*)EI);

    zero_kernel<<<NB, 256>>>();
    count_kernel<<<(NE + 255) / 256, 256>>>(EI);
    scan1_kernel<<<NB, 256>>>();
    scan2_kernel<<<1, 512>>>();
    scan3_kernel<<<NB, 256>>>();
    fill_kernel<<<(NE + 255) / 256, 256>>>(EI);

    int smem = D * D * (int)sizeof(float);   // 64 KB
    cudaFuncSetAttribute(gemm_kernel,
                         cudaFuncAttributeMaxDynamicSharedMemorySize, smem);
    gemm_kernel<<<N_NODES / (32 * TILES_PER_BLOCK), 256, smem>>>(X, W);

    gather_kernel<<<(N_NODES * 32 + 255) / 256, 256>>>(out);
}

// round 6
// speedup vs baseline: 1.9932x; 1.1505x over previous
#include <cuda_runtime.h>
#include <cuda_fp16.h>
#include <mma.h>
#include <cstdint>

using namespace nvcuda;

#define N_NODES 100000
#define NE      1600000
#define D       128
#define NB      ((N_NODES + 255) / 256)   // 391 scan blocks

// Scratch (__device__ globals; no allocation)
__device__ __align__(16) __half g_Yh[(size_t)N_NODES * D];  // 25.6 MB, Y = X@W in fp16
__device__ int g_degi[N_NODES];
__device__ int g_rowstart[N_NODES];
__device__ int g_cursor[N_NODES];
__device__ int g_adj[2 * NE];                               // 12.8 MB
__device__ int g_bsum[512];
__device__ int g_is64;

// ---------------------------------------------------------------------------
// Probe edge dtype: int64 (high words of ring edges are 0) vs int32.
// ---------------------------------------------------------------------------
__global__ void probe_kernel(const int* __restrict__ ei) {
    int acc = 0;
#pragma unroll
    for (int i = 1; i < 32; i += 2) acc |= ei[i];
    g_is64 = (acc == 0) ? 1 : 0;
}

__device__ __forceinline__ void load_edge(const void* ei_raw, int e, int& s, int& d) {
    if (g_is64) {
        const long long* ei = (const long long*)ei_raw;
        s = (int)ei[e];
        d = (int)ei[NE + e];
    } else {
        const int* ei = (const int*)ei_raw;
        s = ei[e];
        d = ei[NE + e];
    }
}

// ---------------------------------------------------------------------------
// CSR build
// ---------------------------------------------------------------------------
__global__ void zero_kernel() {
    int i = blockIdx.x * blockDim.x + threadIdx.x;
    if (i < N_NODES) g_degi[i] = 0;
}

__global__ void count_kernel(const void* __restrict__ ei_raw) {
    int e = blockIdx.x * blockDim.x + threadIdx.x;
    if (e >= NE) return;
    int s, d;
    load_edge(ei_raw, e, s, d);
    atomicAdd(&g_degi[s], 1);
    atomicAdd(&g_degi[d], 1);
}

__global__ void scan1_kernel() {
    __shared__ int sh[256];
    int tid = threadIdx.x;
    int i   = blockIdx.x * 256 + tid;
    int v   = (i < N_NODES) ? g_degi[i] : 0;
    sh[tid] = v;
    __syncthreads();
#pragma unroll
    for (int off = 1; off < 256; off <<= 1) {
        int t = (tid >= off) ? sh[tid - off] : 0;
        __syncthreads();
        sh[tid] += t;
        __syncthreads();
    }
    if (i < N_NODES) g_rowstart[i] = sh[tid] - v;
    if (tid == 255) g_bsum[blockIdx.x] = sh[255];
}

__global__ void scan2_kernel() {
    __shared__ int sh[512];
    int tid = threadIdx.x;
    int v   = (tid < NB) ? g_bsum[tid] : 0;
    sh[tid] = v;
    __syncthreads();
#pragma unroll
    for (int off = 1; off < 512; off <<= 1) {
        int t = (tid >= off) ? sh[tid - off] : 0;
        __syncthreads();
        sh[tid] += t;
        __syncthreads();
    }
    if (tid < NB) g_bsum[tid] = sh[tid] - v;   // exclusive
}

__global__ void scan3_kernel() {
    int i = blockIdx.x * 256 + threadIdx.x;
    if (i >= N_NODES) return;
    int r = g_rowstart[i] + g_bsum[blockIdx.x];
    g_rowstart[i] = r;
    g_cursor[i]   = r;
}

__global__ void fill_kernel(const void* __restrict__ ei_raw) {
    int e = blockIdx.x * blockDim.x + threadIdx.x;
    if (e >= NE) return;
    int s, d;
    load_edge(ei_raw, e, s, d);
    int p = atomicAdd(&g_cursor[s], 1);
    g_adj[p] = d;
    int q = atomicAdd(&g_cursor[d], 1);
    g_adj[q] = s;
}

// ---------------------------------------------------------------------------
// GEMM: Yh = half(X @ W)  via tf32 wmma (m16n16k8).
// 8 warps/block; warp w computes rows [blk*128 + w*16, +16) x all 128 cols
// as 8 accumulator fragments. W staged in 64 KB smem; after the k-loop the
// same smem is reused as C staging for coalesced fp16 packing.
// ---------------------------------------------------------------------------
#define GEMM_ROWS_PER_BLOCK 128

__global__ void __launch_bounds__(256, 2)
gemm_kernel(const float* __restrict__ X, const float* __restrict__ W) {
    extern __shared__ float sh[];     // 128*128 floats = 64 KB

    int tid  = threadIdx.x;
    int warp = tid >> 5;
    int lane = tid & 31;

    // Stage W
    const float4* W4  = (const float4*)W;
    float4*       sh4 = (float4*)sh;
#pragma unroll
    for (int i = 0; i < 16; i++) sh4[tid + i * 256] = W4[tid + i * 256];
    __syncthreads();

    int row0    = blockIdx.x * GEMM_ROWS_PER_BLOCK + warp * 16;
    bool active = (row0 < N_NODES);

    wmma::fragment<wmma::accumulator, 16, 16, 8, float> c[8];
    if (active) {
#pragma unroll
        for (int n = 0; n < 8; n++) wmma::fill_fragment(c[n], 0.0f);

        const float* a_base = X + (size_t)row0 * D;
#pragma unroll 1
        for (int kc = 0; kc < 16; kc++) {
            wmma::fragment<wmma::matrix_a, 16, 16, 8, wmma::precision::tf32, wmma::row_major> a;
            wmma::load_matrix_sync(a, a_base + kc * 8, D);
#pragma unroll
            for (int t = 0; t < a.num_elements; t++) a.x[t] = wmma::__float_to_tf32(a.x[t]);

#pragma unroll
            for (int n = 0; n < 8; n++) {
                wmma::fragment<wmma::matrix_b, 16, 16, 8, wmma::precision::tf32, wmma::row_major> b;
                wmma::load_matrix_sync(b, sh + (kc * 8) * D + n * 16, D);
#pragma unroll
                for (int t = 0; t < b.num_elements; t++) b.x[t] = wmma::__float_to_tf32(b.x[t]);
                wmma::mma_sync(c[n], a, b, c[n]);
            }
        }
    }

    __syncthreads();   // W no longer needed; reuse sh as C staging

    if (active) {
        float* cstg = sh + warp * 16 * D;   // 16 rows x 128 cols per warp
#pragma unroll
        for (int n = 0; n < 8; n++)
            wmma::store_matrix_sync(cstg + n * 16, c[n], D, wmma::mem_row_major);
        __syncwarp();

        // Pack to fp16 and write: 16 rows x 128 cols; lane covers 4 cols/row.
#pragma unroll
        for (int r = 0; r < 16; r++) {
            float4 v = ((const float4*)(cstg + r * D))[lane];
            __half2 h01 = __float22half2_rn(make_float2(v.x, v.y));
            __half2 h23 = __float22half2_rn(make_float2(v.z, v.w));
            uint2 packed;
            packed.x = *(unsigned*)&h01;
            packed.y = *(unsigned*)&h23;
            ((uint2*)(g_Yh + (size_t)(row0 + r) * D))[lane] = packed;
        }
    }
}

// ---------------------------------------------------------------------------
// Gather: out[i] = relu((Y[i] + sum_{j in adj[i]} Y[j]) / deg[i])
// One warp per node; fp16 rows (256B), fp32 accumulation.
// ---------------------------------------------------------------------------
__device__ __forceinline__ void acc_half4(float4& acc, uint2 raw) {
    __half2 h01 = *(__half2*)&raw.x;
    __half2 h23 = *(__half2*)&raw.y;
    float2 f01 = __half22float2(h01);
    float2 f23 = __half22float2(h23);
    acc.x += f01.x; acc.y += f01.y; acc.z += f23.x; acc.w += f23.y;
}

__global__ void __launch_bounds__(256)
gather_kernel(float* __restrict__ out) {
    int w    = (blockIdx.x * blockDim.x + threadIdx.x) >> 5;
    int lane = threadIdx.x & 31;
    if (w >= N_NODES) return;

    int base = g_rowstart[w];
    int degn = g_degi[w];

    const uint2* Y2 = (const uint2*)g_Yh;
    float4 acc = make_float4(0.f, 0.f, 0.f, 0.f);
    acc_half4(acc, __ldg(Y2 + (size_t)w * 32 + lane));   // self term

    for (int t = 0; t < degn; t += 32) {
        int cnt   = min(32, degn - t);
        int myidx = (lane < cnt) ? g_adj[base + t + lane] : 0;
#pragma unroll 8
        for (int k = 0; k < cnt; k++) {
            int u = __shfl_sync(0xffffffffu, myidx, k);
            acc_half4(acc, __ldg(Y2 + (size_t)u * 32 + lane));
        }
    }

    float inv = 1.0f / (float)degn;
    float4 o;
    o.x = fmaxf(acc.x * inv, 0.0f);
    o.y = fmaxf(acc.y * inv, 0.0f);
    o.z = fmaxf(acc.z * inv, 0.0f);
    o.w = fmaxf(acc.w * inv, 0.0f);
    ((float4*)out)[(size_t)w * 32 + lane] = o;
}

// ---------------------------------------------------------------------------
extern "C" void kernel_launch(void* const* d_in, const int* in_sizes, int n_in,
                              void* d_out, int out_size) {
    const float* X   = (const float*)d_in[0];
    const float* W   = (const float*)d_in[1];
    const void*  EI  = d_in[2];
    float*       out = (float*)d_out;

    probe_kernel<<<1, 1>>>((const int*)EI);

    zero_kernel<<<NB, 256>>>();
    count_kernel<<<(NE + 255) / 256, 256>>>(EI);
    scan1_kernel<<<NB, 256>>>();
    scan2_kernel<<<1, 512>>>();
    scan3_kernel<<<NB, 256>>>();
    fill_kernel<<<(NE + 255) / 256, 256>>>(EI);

    int smem = D * D * (int)sizeof(float);   // 64 KB
    cudaFuncSetAttribute(gemm_kernel,
                         cudaFuncAttributeMaxDynamicSharedMemorySize, smem);
    int gemm_grid = (N_NODES + GEMM_ROWS_PER_BLOCK - 1) / GEMM_ROWS_PER_BLOCK;  // 782
    gemm_kernel<<<gemm_grid, 256, smem>>>(X, W);

    gather_kernel<<<(N_NODES * 32 + 255) / 256, 256>>>(out);
}

// round 8
// speedup vs baseline: 2.1422x; 1.0747x over previous
#include <cuda_runtime.h>
#include <cuda_fp16.h>
#include <mma.h>
#include <cstdint>

using namespace nvcuda;

#define N_NODES 100000
#define NE      1600000
#define D       128
#define NB      ((N_NODES + 255) / 256)     // 391 scan blocks

#define GEMM_TILES       782                 // 128 rows each
#define GEMM_TILES_A     391                 // tiles in fused_A
#define GEMM_TILES_B     (GEMM_TILES - GEMM_TILES_A)
#define EDGE_BLOCKS      1563                // 1024 edges per block (256 thr x 4)

// Scratch (__device__ globals; no allocation)
__device__ __align__(16) __half g_Yh[(size_t)N_NODES * D];  // 25.6 MB
__device__ int g_degi[N_NODES];
__device__ int g_rowstart[N_NODES];
__device__ int g_cursor[N_NODES];
__device__ int g_adj[2 * NE];                               // 12.8 MB
__device__ int g_bsum[512];
__device__ int g_is64;

// ---------------------------------------------------------------------------
__device__ __forceinline__ void load_edge(const void* ei_raw, int e, int& s, int& d) {
    if (g_is64) {
        const long long* ei = (const long long*)ei_raw;
        s = (int)ei[e];
        d = (int)ei[NE + e];
    } else {
        const int* ei = (const int*)ei_raw;
        s = ei[e];
        d = ei[NE + e];
    }
}

// ---------------------------------------------------------------------------
// probe (thread 0 of block 0) + zero degrees. Probe: ring edges are small,
// so for int64 the odd 32-bit words are 0; for int32 they are 1,3,5,...
// ---------------------------------------------------------------------------
__global__ void probe_zero_kernel(const int* __restrict__ ei) {
    int i = blockIdx.x * blockDim.x + threadIdx.x;
    if (i == 0) {
        int acc = 0;
#pragma unroll
        for (int k = 1; k < 32; k += 2) acc |= ei[k];
        g_is64 = (acc == 0) ? 1 : 0;
    }
    if (i < N_NODES) g_degi[i] = 0;
}

// ---------------------------------------------------------------------------
// GEMM tile (tf32 wmma m16n16k8): rows [tile*128, +128) of Yh = half(X@W).
// sh = 64 KB: W while accumulating, then C staging.
// ---------------------------------------------------------------------------
__device__ __forceinline__ void gemm_tile(int tile, const float* __restrict__ X,
                                          const float* __restrict__ W, float* sh) {
    int tid  = threadIdx.x;
    int warp = tid >> 5;
    int lane = tid & 31;

    const float4* W4  = (const float4*)W;
    float4*       sh4 = (float4*)sh;
#pragma unroll
    for (int i = 0; i < 16; i++) sh4[tid + i * 256] = W4[tid + i * 256];
    __syncthreads();

    int row0    = tile * 128 + warp * 16;
    bool active = (row0 < N_NODES);

    wmma::fragment<wmma::accumulator, 16, 16, 8, float> c[8];
    if (active) {
#pragma unroll
        for (int n = 0; n < 8; n++) wmma::fill_fragment(c[n], 0.0f);

        const float* a_base = X + (size_t)row0 * D;
#pragma unroll 1
        for (int kc = 0; kc < 16; kc++) {
            wmma::fragment<wmma::matrix_a, 16, 16, 8, wmma::precision::tf32, wmma::row_major> a;
            wmma::load_matrix_sync(a, a_base + kc * 8, D);
#pragma unroll
            for (int t = 0; t < a.num_elements; t++) a.x[t] = wmma::__float_to_tf32(a.x[t]);
#pragma unroll
            for (int n = 0; n < 8; n++) {
                wmma::fragment<wmma::matrix_b, 16, 16, 8, wmma::precision::tf32, wmma::row_major> b;
                wmma::load_matrix_sync(b, sh + (kc * 8) * D + n * 16, D);
#pragma unroll
                for (int t = 0; t < b.num_elements; t++) b.x[t] = wmma::__float_to_tf32(b.x[t]);
                wmma::mma_sync(c[n], a, b, c[n]);
            }
        }
    }

    __syncthreads();   // W done; reuse sh for C staging

    if (active) {
        float* cstg = sh + warp * 16 * D;
#pragma unroll
        for (int n = 0; n < 8; n++)
            wmma::store_matrix_sync(cstg + n * 16, c[n], D, wmma::mem_row_major);
        __syncwarp();
#pragma unroll
        for (int r = 0; r < 16; r++) {
            float4 v = ((const float4*)(cstg + r * D))[lane];
            __half2 h01 = __float22half2_rn(make_float2(v.x, v.y));
            __half2 h23 = __float22half2_rn(make_float2(v.z, v.w));
            uint2 packed;
            packed.x = *(unsigned*)&h01;
            packed.y = *(unsigned*)&h23;
            ((uint2*)(g_Yh + (size_t)(row0 + r) * D))[lane] = packed;
        }
    }
}

// ---------------------------------------------------------------------------
// fused_A: blocks [0,391) = GEMM tiles 0..390; rest = degree count (4 e/thr).
// ---------------------------------------------------------------------------
__global__ void __launch_bounds__(256)
fused_A_kernel(const float* __restrict__ X, const float* __restrict__ W,
               const void* __restrict__ ei_raw) {
    extern __shared__ float sh[];
    if (blockIdx.x < GEMM_TILES_A) {
        gemm_tile(blockIdx.x, X, W, sh);
        return;
    }
    int cb   = blockIdx.x - GEMM_TILES_A;
    int base = cb * 1024 + threadIdx.x;
#pragma unroll
    for (int j = 0; j < 4; j++) {
        int e = base + j * 256;
        if (e < NE) {
            int s, d;
            load_edge(ei_raw, e, s, d);
            atomicAdd(&g_degi[s], 1);
            atomicAdd(&g_degi[d], 1);
        }
    }
}

// ---------------------------------------------------------------------------
// Scan chain (deg -> rowstart exclusive prefix)
// ---------------------------------------------------------------------------
__global__ void scan1_kernel() {
    __shared__ int sh[256];
    int tid = threadIdx.x;
    int i   = blockIdx.x * 256 + tid;
    int v   = (i < N_NODES) ? g_degi[i] : 0;
    sh[tid] = v;
    __syncthreads();
#pragma unroll
    for (int off = 1; off < 256; off <<= 1) {
        int t = (tid >= off) ? sh[tid - off] : 0;
        __syncthreads();
        sh[tid] += t;
        __syncthreads();
    }
    if (i < N_NODES) g_rowstart[i] = sh[tid] - v;
    if (tid == 255) g_bsum[blockIdx.x] = sh[255];
}

__global__ void scan2_kernel() {
    __shared__ int sh[512];
    int tid = threadIdx.x;
    int v   = (tid < NB) ? g_bsum[tid] : 0;
    sh[tid] = v;
    __syncthreads();
#pragma unroll
    for (int off = 1; off < 512; off <<= 1) {
        int t = (tid >= off) ? sh[tid - off] : 0;
        __syncthreads();
        sh[tid] += t;
        __syncthreads();
    }
    if (tid < NB) g_bsum[tid] = sh[tid] - v;   // exclusive
}

__global__ void scan3_kernel() {
    int i = blockIdx.x * 256 + threadIdx.x;
    if (i >= N_NODES) return;
    int r = g_rowstart[i] + g_bsum[blockIdx.x];
    g_rowstart[i] = r;
    g_cursor[i]   = r;
}

// ---------------------------------------------------------------------------
// fused_B: blocks [0,391) = GEMM tiles 391..781; rest = CSR fill (4 e/thr).
// ---------------------------------------------------------------------------
__global__ void __launch_bounds__(256)
fused_B_kernel(const float* __restrict__ X, const float* __restrict__ W,
               const void* __restrict__ ei_raw) {
    extern __shared__ float sh[];
    if (blockIdx.x < GEMM_TILES_B) {
        gemm_tile(GEMM_TILES_A + blockIdx.x, X, W, sh);
        return;
    }
    int fb   = blockIdx.x - GEMM_TILES_B;
    int base = fb * 1024 + threadIdx.x;
#pragma unroll
    for (int j = 0; j < 4; j++) {
        int e = base + j * 256;
        if (e < NE) {
            int s, d;
            load_edge(ei_raw, e, s, d);
            int p = atomicAdd(&g_cursor[s], 1);
            g_adj[p] = d;
            int q = atomicAdd(&g_cursor[d], 1);
            g_adj[q] = s;
        }
    }
}

// ---------------------------------------------------------------------------
// Gather: out[i] = relu((Y[i] + sum_{j in adj[i]} Y[j]) / deg[i])
// ---------------------------------------------------------------------------
__device__ __forceinline__ void acc_half4(float4& acc, uint2 raw) {
    __half2 h01 = *(__half2*)&raw.x;
    __half2 h23 = *(__half2*)&raw.y;
    float2 f01 = __half22float2(h01);
    float2 f23 = __half22float2(h23);
    acc.x += f01.x; acc.y += f01.y; acc.z += f23.x; acc.w += f23.y;
}

__global__ void __launch_bounds__(256)
gather_kernel(float* __restrict__ out) {
    int w    = (blockIdx.x * blockDim.x + threadIdx.x) >> 5;
    int lane = threadIdx.x & 31;
    if (w >= N_NODES) return;

    int base = g_rowstart[w];
    int degn = g_degi[w];

    const uint2* Y2 = (const uint2*)g_Yh;
    float4 acc = make_float4(0.f, 0.f, 0.f, 0.f);
    acc_half4(acc, __ldg(Y2 + (size_t)w * 32 + lane));   // self term

    for (int t = 0; t < degn; t += 32) {
        int cnt   = min(32, degn - t);
        int myidx = (lane < cnt) ? g_adj[base + t + lane] : 0;
#pragma unroll 8
        for (int k = 0; k < cnt; k++) {
            int u = __shfl_sync(0xffffffffu, myidx, k);
            acc_half4(acc, __ldg(Y2 + (size_t)u * 32 + lane));
        }
    }

    float inv = 1.0f / (float)degn;
    float4 o;
    o.x = fmaxf(acc.x * inv, 0.0f);
    o.y = fmaxf(acc.y * inv, 0.0f);
    o.z = fmaxf(acc.z * inv, 0.0f);
    o.w = fmaxf(acc.w * inv, 0.0f);
    ((float4*)out)[(size_t)w * 32 + lane] = o;
}

// ---------------------------------------------------------------------------
extern "C" void kernel_launch(void* const* d_in, const int* in_sizes, int n_in,
                              void* d_out, int out_size) {
    const float* X   = (const float*)d_in[0];
    const float* W   = (const float*)d_in[1];
    const void*  EI  = d_in[2];
    float*       out = (float*)d_out;

    int smem = D * D * (int)sizeof(float);   // 64 KB
    cudaFuncSetAttribute(fused_A_kernel,
                         cudaFuncAttributeMaxDynamicSharedMemorySize, smem);
    cudaFuncSetAttribute(fused_B_kernel,
                         cudaFuncAttributeMaxDynamicSharedMemorySize, smem);

    probe_zero_kernel<<<NB, 256>>>((const int*)EI);

    fused_A_kernel<<<GEMM_TILES_A + EDGE_BLOCKS, 256, smem>>>(X, W, EI);

    scan1_kernel<<<NB, 256>>>();
    scan2_kernel<<<1, 512>>>();
    scan3_kernel<<<NB, 256>>>();

    fused_B_kernel<<<GEMM_TILES_B + EDGE_BLOCKS, 256, smem>>>(X, W, EI);

    gather_kernel<<<(N_NODES * 32 + 255) / 256, 256>>>(out);
}